// round 5
// baseline (speedup 1.0000x reference)
#include <cuda_runtime.h>

#define NSER 8192
#define OBS 9
#define NBLK 128
#define SPC 64            // series per CTA
#define TPB 128           // 4 warps: 0,1 = A (measurement), 2,3 = B (covariance)
#define LOG2PI_F 1.8378770664093453f

static __device__ double g_partials[NBLK];

// sym index tables for 4x4 upper triangle
__device__ __constant__ int SL[10] = {0,0,0,0,1,1,1,2,2,3};
__device__ __constant__ int SJ[10] = {0,1,2,3,1,2,3,2,3,3};

__global__ void __launch_bounds__(TPB) kf_kernel(
    const float* __restrict__ y,
    const float* __restrict__ B1s1_p,
    const float* __restrict__ B1s2_p,
    const float* __restrict__ lam1_p,
    const float* __restrict__ lam2_p,
    const float* __restrict__ logq_p,
    const float* __restrict__ logr_p,
    const float* __restrict__ gami_p,
    const float* __restrict__ gamc_p,
    int NT)
{
    const int tid = threadIdx.x;
    const bool isA = tid < SPC;
    const int s = isA ? tid : (tid - SPC);        // series slot in CTA
    const int n = blockIdx.x * SPC + s;           // global series

    // exchange buffers (odd strides -> conflict-free)
    __shared__ float sPp[SPC][11];    // 10 sym entries of Pp
    __shared__ float sW[SPC][9];      // W00,W01,W02,W11,W12,W22, logdetS (7 used)
    __shared__ float sX[SPC][15];     // X2[10], d1[4], pt1
    __shared__ double sRed[2];

    // ---------------- shared-constant prep (both roles read tiny inputs) ----------------
    float Bm[3][3];
#pragma unroll
    for (int i = 0; i < 3; ++i)
#pragma unroll
        for (int j = 0; j < 3; ++j)
            Bm[i][j] = B1s1_p[i * 3 + j];
    const float b3 = B1s2_p[0];

    float a1[3] = {0.f, 0.f, 0.f};
    float a2 = 0.f;
    float dinv[9], cd1[9], cd2[9];
    float logdetD = 0.f;
    {
        float c1[9], c2[9];
        c1[0] = 1.f; c1[1] = lam1_p[0]; c1[2] = lam1_p[1];
        c1[3] = 1.f; c1[4] = lam1_p[2]; c1[5] = lam1_p[3];
        c1[6] = 1.f; c1[7] = lam1_p[4]; c1[8] = lam1_p[5];
        c2[0] = 1.f;
#pragma unroll
        for (int o = 1; o < 9; ++o) c2[o] = lam2_p[o - 1];
#pragma unroll
        for (int o = 0; o < 9; ++o) {
            float r = expf(logr_p[o]);
            float d = r + 1e-6f;
            float di = 1.f / d;
            dinv[o] = di;
            cd1[o] = c1[o] * di;
            cd2[o] = c2[o] * di;
            logdetD += logf(d);
            a1[o / 3] += c1[o] * c1[o] * di;
            a2 += c2[o] * c2[o] * di;
        }
    }
    const float CK = -0.5f * (9.f * LOG2PI_F + logdetD);
    const float g0 = gami_p[0];
    const float gc0 = gamc_p[0], gc1 = gamc_p[1], gc2 = gamc_p[2];
    float q[4];
#pragma unroll
    for (int l = 0; l < 4; ++l) q[l] = expf(logq_p[l]);

    // ---------------- role state ----------------
    // B-side
    float P[4][4];
#pragma unroll
    for (int i = 0; i < 4; ++i)
#pragma unroll
        for (int j = 0; j < 4; ++j)
            P[i][j] = (i == j) ? 1000.f : 0.f;
    float P1u[10];
    // A-side
    float eta[4] = {0.f, 0.f, 0.f, 0.f};
    float p1 = 0.99f, p2 = 0.01f;
    double ll = 0.0;
    const float* yp = y + (size_t)n * NT * OBS;
    float yc[9];
    if (isA) {
#pragma unroll
        for (int o = 0; o < 9; ++o) yc[o] = yp[o];
    }

    // A phase-X -> phase-Y carriers
    float ep[4], uu[3], u2s, quadD1, quadD2, p11, p12, yn[9];

#pragma unroll 1
    for (int t = 0; t < NT; ++t) {
        // ================= PHASE X =================
        if (isA) {
            // prefetch next y
            const float* ynp = yp + (t + 1) * OBS;
            const bool have = (t + 1) < NT;
#pragma unroll
            for (int o = 0; o < 9; ++o) yn[o] = have ? ynp[o] : 0.f;

            // transition prob (pre-update eta)
            float lg = g0 + gc0 * eta[0] + gc1 * eta[1] + gc2 * eta[2];
            p11 = __fdividef(1.f, 1.f + __expf(-lg));
            p12 = 1.f - p11;

            // eta_pred
            ep[0] = Bm[0][0] * eta[0] + Bm[0][1] * eta[1] + Bm[0][2] * eta[2];
            ep[1] = Bm[1][0] * eta[0] + Bm[1][1] * eta[1] + Bm[1][2] * eta[2];
            ep[2] = Bm[2][0] * eta[0] + Bm[2][1] * eta[1] + Bm[2][2] * eta[2];
            ep[3] = b3 * eta[3];

            // y-precomputes (expanded quadratic forms)
            float Yq = 0.f, Y1[3] = {0.f, 0.f, 0.f}, Y2 = 0.f;
#pragma unroll
            for (int o = 0; o < 9; ++o) {
                Yq += yc[o] * yc[o] * dinv[o];
                Y1[o / 3] += yc[o] * cd1[o];
                Y2 += yc[o] * cd2[o];
            }
            quadD1 = Yq; quadD2 = Yq;
#pragma unroll
            for (int g = 0; g < 3; ++g) {
                uu[g] = Y1[g] - a1[g] * ep[g];
                quadD1 += ep[g] * (a1[g] * ep[g] - 2.f * Y1[g]);
            }
            u2s = Y2 - a2 * ep[3];
            quadD2 += ep[3] * (a2 * ep[3] - 2.f * Y2);
        } else {
            // finalize previous step's posterior P (needs A's X2/d1/pt1 of t-1)
            if (t > 0) {
                float d1v[4];
#pragma unroll
                for (int l = 0; l < 4; ++l) d1v[l] = sX[s][10 + l];
                float pt1r = sX[s][14];
#pragma unroll
                for (int k = 0; k < 10; ++k) {
                    float t1 = P1u[k] + d1v[SL[k]] * d1v[SJ[k]];
                    float pn = fmaf(pt1r, t1, sX[s][k]);
                    P[SL[k]][SJ[k]] = pn; P[SJ[k]][SL[k]] = pn;
                }
            }

            // P_pred = Bt P Bt^T + Q (block structure)
            float T[4][4];
#pragma unroll
            for (int i = 0; i < 3; ++i)
#pragma unroll
                for (int j = 0; j < 4; ++j)
                    T[i][j] = Bm[i][0] * P[0][j] + Bm[i][1] * P[1][j] + Bm[i][2] * P[2][j];
#pragma unroll
            for (int j = 0; j < 4; ++j) T[3][j] = b3 * P[3][j];

            float Pp[4][4];
#pragma unroll
            for (int i = 0; i < 4; ++i) {
#pragma unroll
                for (int j = i; j < 4; ++j) {
                    float v = (j < 3)
                            ? T[i][0] * Bm[j][0] + T[i][1] * Bm[j][1] + T[i][2] * Bm[j][2]
                            : T[i][3] * b3;
                    Pp[i][j] = v; Pp[j][i] = v;
                }
            }
            Pp[0][0] += q[0]; Pp[1][1] += q[1]; Pp[2][2] += q[2]; Pp[3][3] += q[3];

#pragma unroll
            for (int k = 0; k < 10; ++k) sPp[s][k] = Pp[SL[k]][SJ[k]];

            // W = (M^-1 + diag(a1))^-1 via S = I + M diag(a1); logdetF1 part = log detS
            float m00 = Pp[0][0], m01 = Pp[0][1], m02 = Pp[0][2];
            float m11 = Pp[1][1], m12 = Pp[1][2], m22 = Pp[2][2];
            float S00 = 1.f + m00 * a1[0], S01 = m01 * a1[1], S02 = m02 * a1[2];
            float S10 = m01 * a1[0], S11 = 1.f + m11 * a1[1], S12 = m12 * a1[2];
            float S20 = m02 * a1[0], S21 = m12 * a1[1], S22 = 1.f + m22 * a1[2];

            float adj00 = S11 * S22 - S12 * S21;
            float adj01 = S02 * S21 - S01 * S22;
            float adj02 = S01 * S12 - S02 * S11;
            float adj10 = S12 * S20 - S10 * S22;
            float adj11 = S00 * S22 - S02 * S20;
            float adj12 = S02 * S10 - S00 * S12;
            float adj20 = S10 * S21 - S11 * S20;
            float adj21 = S01 * S20 - S00 * S21;
            float adj22 = S00 * S11 - S01 * S10;
            float detS = S00 * adj00 + S01 * adj10 + S02 * adj20;
            float idS = __fdividef(1.f, detS);

            float W00 = idS * (adj00 * m00 + adj01 * m01 + adj02 * m02);
            float W01 = idS * (adj00 * m01 + adj01 * m11 + adj02 * m12);
            float W02 = idS * (adj00 * m02 + adj01 * m12 + adj02 * m22);
            float W11 = idS * (adj10 * m01 + adj11 * m11 + adj12 * m12);
            float W12 = idS * (adj10 * m02 + adj11 * m12 + adj12 * m22);
            float W22 = idS * (adj20 * m02 + adj21 * m12 + adj22 * m22);

            sW[s][0] = W00; sW[s][1] = W01; sW[s][2] = W02;
            sW[s][3] = W11; sW[s][4] = W12; sW[s][5] = W22;
            sW[s][6] = __logf(detS);

            // stash Pp for phase Y in registers (reuse T)
#pragma unroll
            for (int i = 0; i < 4; ++i)
#pragma unroll
                for (int j = 0; j < 4; ++j) T[i][j] = Pp[i][j];
            // keep in P1u-unused? store to P (P is dead until next finalize) :
#pragma unroll
            for (int i = 0; i < 4; ++i)
#pragma unroll
                for (int j = 0; j < 4; ++j) P[i][j] = T[i][j];
        }
        __syncthreads();

        // ================= PHASE Y =================
        if (isA) {
            float pp00 = sPp[s][0], pp01 = sPp[s][1], pp02 = sPp[s][2], pp03 = sPp[s][3];
            float pp11 = sPp[s][4], pp12 = sPp[s][5], pp13 = sPp[s][6];
            float pp22 = sPp[s][7], pp23 = sPp[s][8], pp33 = sPp[s][9];
            float W00 = sW[s][0], W01 = sW[s][1], W02 = sW[s][2];
            float W11 = sW[s][3], W12 = sW[s][4], W22 = sW[s][5];
            float logdetS = sW[s][6];

            // regime 2
            float den = 1.f + pp33 * a2;
            float iden = __fdividef(1.f, den);
            float k2[4];
            k2[0] = pp03 * iden; k2[1] = pp13 * iden; k2[2] = pp23 * iden; k2[3] = pp33 * iden;
            float quad2 = quadD2 - pp33 * u2s * u2s * iden;
            float lp2 = -0.5f * (quad2 + __logf(den)) + CK;
            float eta2[4];
#pragma unroll
            for (int l = 0; l < 4; ++l) eta2[l] = ep[l] + k2[l] * u2s;

            // regime 1
            float wu0 = W00 * uu[0] + W01 * uu[1] + W02 * uu[2];
            float wu1 = W01 * uu[0] + W11 * uu[1] + W12 * uu[2];
            float wu2 = W02 * uu[0] + W12 * uu[1] + W22 * uu[2];
            float uWu = uu[0] * wu0 + uu[1] * wu1 + uu[2] * wu2;
            float quad1 = quadD1 - uWu;
            float lp1 = -0.5f * (quad1 + logdetS) + CK;

            float gu0 = uu[0] - a1[0] * wu0;
            float gu1 = uu[1] - a1[1] * wu1;
            float gu2 = uu[2] - a1[2] * wu2;
            float eta1[4];
            eta1[0] = ep[0] + pp00 * gu0 + pp01 * gu1 + pp02 * gu2;
            eta1[1] = ep[1] + pp01 * gu0 + pp11 * gu1 + pp12 * gu2;
            eta1[2] = ep[2] + pp02 * gu0 + pp12 * gu1 + pp22 * gu2;
            eta1[3] = ep[3] + pp03 * gu0 + pp13 * gu1 + pp23 * gu2;

            // mixture probs
            float lik1 = __expf(lp1);
            float lik2 = __expf(lp2);
            float num1 = lik1 * (p1 * p11);            // p21 = 0
            float num2 = lik2 * (p1 * p12 + p2);       // p22 = 1
            float marg = num1 + num2 + 1e-9f;
            float im = __fdividef(1.f, marg);
            float pt1 = num1 * im, pt2 = num2 * im;
            ll += (double)__logf(marg);

            float d1v[4], d2v[4];
#pragma unroll
            for (int l = 0; l < 4; ++l) {
                float e = pt1 * eta1[l] + pt2 * eta2[l];
                d1v[l] = eta1[l] - e;
                d2v[l] = eta2[l] - e;
                eta[l] = e;
            }

            // P2u = Pp - a2*k2 (x) Pp[3,:], then X2 = pt2*(P2u + d2 d2^T)
            float ak0 = a2 * k2[0], ak1 = a2 * k2[1], ak2 = a2 * k2[2], ak3 = a2 * k2[3];
            float P2u[10];
            P2u[0] = pp00 - ak0 * pp03;
            P2u[1] = pp01 - ak0 * pp13;
            P2u[2] = pp02 - ak0 * pp23;
            P2u[3] = pp03 - ak0 * pp33;
            P2u[4] = pp11 - ak1 * pp13;
            P2u[5] = pp12 - ak1 * pp23;
            P2u[6] = pp13 - ak1 * pp33;
            P2u[7] = pp22 - ak2 * pp23;
            P2u[8] = pp23 - ak2 * pp33;
            P2u[9] = pp33 - ak3 * pp33;
#pragma unroll
            for (int k = 0; k < 10; ++k)
                sX[s][k] = pt2 * (P2u[k] + d2v[SL[k]] * d2v[SJ[k]]);
#pragma unroll
            for (int l = 0; l < 4; ++l) sX[s][10 + l] = d1v[l];
            sX[s][14] = pt1;

            p1 = pt1; p2 = pt2;
#pragma unroll
            for (int o = 0; o < 9; ++o) yc[o] = yn[o];
        } else {
            // Kalman gain core + short-form P1 (Pp held in P registers)
            float W00 = sW[s][0], W01 = sW[s][1], W02 = sW[s][2];
            float W11 = sW[s][3], W12 = sW[s][4], W22 = sW[s][5];
            float G00 = 1.f - a1[0] * W00, G01 = -a1[0] * W01, G02 = -a1[0] * W02;
            float G10 = -a1[1] * W01, G11 = 1.f - a1[1] * W11, G12 = -a1[1] * W12;
            float G20 = -a1[2] * W02, G21 = -a1[2] * W12, G22 = 1.f - a1[2] * W22;

            float Ka[4][3];
#pragma unroll
            for (int l = 0; l < 4; ++l) {
                float k0 = P[l][0] * G00 + P[l][1] * G10 + P[l][2] * G20;
                float k1 = P[l][0] * G01 + P[l][1] * G11 + P[l][2] * G21;
                float k2v = P[l][0] * G02 + P[l][1] * G12 + P[l][2] * G22;
                Ka[l][0] = k0 * a1[0];
                Ka[l][1] = k1 * a1[1];
                Ka[l][2] = k2v * a1[2];
            }
#pragma unroll
            for (int k = 0; k < 10; ++k) {
                int l = SL[k], j = SJ[k];
                P1u[k] = P[l][j] - Ka[l][0] * P[0][j]
                                 - Ka[l][1] * P[1][j]
                                 - Ka[l][2] * P[2][j];
            }
        }
        __syncthreads();
    }

    // ---- deterministic reduction (A warps only carry ll) ----
    if (isA) {
        double v = ll;
#pragma unroll
        for (int off = 16; off > 0; off >>= 1)
            v += __shfl_down_sync(0xffffffffu, v, off);
        if ((tid & 31) == 0) sRed[tid >> 5] = v;
    }
    __syncthreads();
    if (tid == 0) g_partials[blockIdx.x] = sRed[0] + sRed[1];
}

__global__ void reduce_kernel(float* out)
{
    __shared__ double sh[NBLK];
    const int t = threadIdx.x;
    sh[t] = g_partials[t];
    __syncthreads();
    for (int k = NBLK / 2; k > 0; k >>= 1) {
        if (t < k) sh[t] += sh[t + k];
        __syncthreads();
    }
    if (t == 0) out[0] = (float)(-sh[0]);
}

extern "C" void kernel_launch(void* const* d_in, const int* in_sizes, int n_in,
                              void* d_out, int out_size)
{
    const float* y    = (const float*)d_in[0];
    const float* B1s1 = (const float*)d_in[1];
    const float* B1s2 = (const float*)d_in[2];
    const float* lam1 = (const float*)d_in[3];
    const float* lam2 = (const float*)d_in[4];
    const float* logq = (const float*)d_in[5];
    const float* logr = (const float*)d_in[6];
    const float* gami = (const float*)d_in[7];
    const float* gamc = (const float*)d_in[8];

    const int NT = in_sizes[0] / (NSER * OBS);   // 400

    kf_kernel<<<NBLK, TPB>>>(y, B1s1, B1s2, lam1, lam2, logq, logr, gami, gamc, NT);
    reduce_kernel<<<1, NBLK>>>((float*)d_out);
}

// round 6
// speedup vs baseline: 1.2683x; 1.2683x over previous
#include <cuda_runtime.h>

#define NSER 8192
#define OBS 9
#define NBLK 128
#define TPB 64
#define LOG2PI_F 1.8378770664093453f

static __device__ double g_partials[NBLK];

// 128 CTAs x 64 threads: <=1 CTA per SM, each CTA's 2 warps on distinct SMSPs
// -> 256 warps on 256 distinct SMSPs, no FMA-pipe sharing (R4 geometry).
__global__ void __launch_bounds__(TPB) kf_kernel(
    const float* __restrict__ y,
    const float* __restrict__ B1s1_p,
    const float* __restrict__ B1s2_p,
    const float* __restrict__ lam1_p,
    const float* __restrict__ lam2_p,
    const float* __restrict__ logq_p,
    const float* __restrict__ logr_p,
    const float* __restrict__ gami_p,
    const float* __restrict__ gamc_p,
    int NT)
{
    const int n = blockIdx.x * TPB + threadIdx.x;

    // ---------------- constants ----------------
    float B[3][3];
#pragma unroll
    for (int i = 0; i < 3; ++i)
#pragma unroll
        for (int j = 0; j < 3; ++j)
            B[i][j] = B1s1_p[i * 3 + j];
    const float b3 = B1s2_p[0];

    float q[4];
#pragma unroll
    for (int l = 0; l < 4; ++l) q[l] = expf(logq_p[l]);

    // cd1 = c1*dinv, cd2 = c2*dinv (for Y precomputes), dinv for Yq
    float dinv[9], cd1[9], cd2[9];
    float a1[3] = {0.f, 0.f, 0.f};
    float a2 = 0.f;
    float logdetD = 0.f;
    {
        float c1[9], c2[9];
        c1[0] = 1.f; c1[1] = lam1_p[0]; c1[2] = lam1_p[1];
        c1[3] = 1.f; c1[4] = lam1_p[2]; c1[5] = lam1_p[3];
        c1[6] = 1.f; c1[7] = lam1_p[4]; c1[8] = lam1_p[5];
        c2[0] = 1.f;
#pragma unroll
        for (int o = 1; o < 9; ++o) c2[o] = lam2_p[o - 1];
#pragma unroll
        for (int o = 0; o < 9; ++o) {
            float r = expf(logr_p[o]);
            float d = r + 1e-6f;
            float di = 1.f / d;
            dinv[o] = di;
            cd1[o] = c1[o] * di;
            cd2[o] = c2[o] * di;
            logdetD += logf(d);
            a1[o / 3] += c1[o] * c1[o] * di;
            a2 += c2[o] * c2[o] * di;
        }
    }
    const float CK = -0.5f * (9.f * LOG2PI_F + logdetD);
    const float g0 = gami_p[0];
    const float gc0 = gamc_p[0], gc1 = gamc_p[1], gc2 = gamc_p[2];

    // ---------------- state ----------------
    float P[4][4];
#pragma unroll
    for (int i = 0; i < 4; ++i)
#pragma unroll
        for (int j = 0; j < 4; ++j)
            P[i][j] = (i == j) ? 1000.f : 0.f;
    float eta[4] = {0.f, 0.f, 0.f, 0.f};
    float p1 = 0.99f, p2 = 0.01f;
    double ll = 0.0;

    const float* yp = y + (size_t)n * NT * OBS;
    float yc[9];
#pragma unroll
    for (int o = 0; o < 9; ++o) yc[o] = yp[o];

#pragma unroll 1
    for (int t = 0; t < NT; ++t) {
        // ---- unconditional clamped prefetch (value dead on last step) ----
        float yn[9];
        {
            int tn = t + 1; if (tn >= NT) tn = NT - 1;
            const float* ynp = yp + tn * OBS;
#pragma unroll
            for (int o = 0; o < 9; ++o) yn[o] = ynp[o];
        }

        // ---- y precomputes (expanded quadratic forms), MLP over the loads ----
        float Yq = 0.f, Y10 = 0.f, Y11 = 0.f, Y12 = 0.f, Y2 = 0.f;
#pragma unroll
        for (int o = 0; o < 9; ++o) {
            float yv = yc[o];
            Yq = fmaf(yv * dinv[o], yv, Yq);
            float t1 = yv * cd1[o];
            if (o < 3) Y10 += t1; else if (o < 6) Y11 += t1; else Y12 += t1;
            Y2 = fmaf(yv, cd2[o], Y2);
        }

        // ---- transition prob (pre-update eta) ----
        float lg = g0 + gc0 * eta[0] + gc1 * eta[1] + gc2 * eta[2];
        float p11 = __fdividef(1.f, 1.f + __expf(-lg));
        float p12 = 1.f - p11;

        // ---- predict ----
        float ep[4];
        ep[0] = B[0][0] * eta[0] + B[0][1] * eta[1] + B[0][2] * eta[2];
        ep[1] = B[1][0] * eta[0] + B[1][1] * eta[1] + B[1][2] * eta[2];
        ep[2] = B[2][0] * eta[0] + B[2][1] * eta[1] + B[2][2] * eta[2];
        ep[3] = b3 * eta[3];

        float T[4][4];
#pragma unroll
        for (int i = 0; i < 3; ++i)
#pragma unroll
            for (int j = 0; j < 4; ++j)
                T[i][j] = B[i][0] * P[0][j] + B[i][1] * P[1][j] + B[i][2] * P[2][j];
#pragma unroll
        for (int j = 0; j < 4; ++j) T[3][j] = b3 * P[3][j];

        float Pp[4][4];
#pragma unroll
        for (int i = 0; i < 4; ++i) {
#pragma unroll
            for (int j = i; j < 4; ++j) {
                float v = (j < 3)
                        ? T[i][0] * B[j][0] + T[i][1] * B[j][1] + T[i][2] * B[j][2]
                        : T[i][3] * b3;
                Pp[i][j] = v; Pp[j][i] = v;
            }
        }
        Pp[0][0] += q[0]; Pp[1][1] += q[1]; Pp[2][2] += q[2]; Pp[3][3] += q[3];

        // ---- innovation stats from expanded forms ----
        // u_g = Y1_g - a1_g*ep_g ;  quadD1 = Yq + sum_g ep_g*(a1_g*ep_g - 2*Y1_g)
        float u0 = Y10 - a1[0] * ep[0];
        float u1 = Y11 - a1[1] * ep[1];
        float u2v = Y12 - a1[2] * ep[2];
        float quadD1 = Yq + ep[0] * fmaf(a1[0], ep[0], -2.f * Y10)
                          + ep[1] * fmaf(a1[1], ep[1], -2.f * Y11)
                          + ep[2] * fmaf(a1[2], ep[2], -2.f * Y12);
        float u2s = Y2 - a2 * ep[3];
        float quadD2 = Yq + ep[3] * fmaf(a2, ep[3], -2.f * Y2);

        // ================= Regime 1: single-inverse Woodbury =================
        // S = I + M*diag(a1);  W = S^-1 M (symmetric);  logdetF1 = logdetD + log detS
        float m00 = Pp[0][0], m01 = Pp[0][1], m02 = Pp[0][2];
        float m11 = Pp[1][1], m12 = Pp[1][2], m22 = Pp[2][2];
        float S00 = 1.f + m00 * a1[0], S01 = m01 * a1[1], S02 = m02 * a1[2];
        float S10 = m01 * a1[0], S11 = 1.f + m11 * a1[1], S12 = m12 * a1[2];
        float S20 = m02 * a1[0], S21 = m12 * a1[1], S22 = 1.f + m22 * a1[2];

        float adj00 = S11 * S22 - S12 * S21;
        float adj01 = S02 * S21 - S01 * S22;
        float adj02 = S01 * S12 - S02 * S11;
        float adj10 = S12 * S20 - S10 * S22;
        float adj11 = S00 * S22 - S02 * S20;
        float adj12 = S02 * S10 - S00 * S12;
        float adj20 = S10 * S21 - S11 * S20;
        float adj21 = S01 * S20 - S00 * S21;
        float adj22 = S00 * S11 - S01 * S10;
        float detS = S00 * adj00 + S01 * adj10 + S02 * adj20;
        float idS = __fdividef(1.f, detS);

        float W00 = idS * (adj00 * m00 + adj01 * m01 + adj02 * m02);
        float W01 = idS * (adj00 * m01 + adj01 * m11 + adj02 * m12);
        float W02 = idS * (adj00 * m02 + adj01 * m12 + adj02 * m22);
        float W11 = idS * (adj10 * m01 + adj11 * m11 + adj12 * m12);
        float W12 = idS * (adj10 * m02 + adj11 * m12 + adj12 * m22);
        float W22 = idS * (adj20 * m02 + adj21 * m12 + adj22 * m22);

        float wu0 = W00 * u0 + W01 * u1 + W02 * u2v;
        float wu1 = W01 * u0 + W11 * u1 + W12 * u2v;
        float wu2 = W02 * u0 + W12 * u1 + W22 * u2v;
        float uWu = u0 * wu0 + u1 * wu1 + u2v * wu2;
        float lp1 = -0.5f * (quadD1 - uWu + __logf(detS)) + CK;

        // G = I - diag(a1) W ;  K1s = Pp[:,0:3] G ;  Ka = K1s diag(a1)
        float G00 = 1.f - a1[0] * W00, G01 = -a1[0] * W01, G02 = -a1[0] * W02;
        float G10 = -a1[1] * W01, G11 = 1.f - a1[1] * W11, G12 = -a1[1] * W12;
        float G20 = -a1[2] * W02, G21 = -a1[2] * W12, G22 = 1.f - a1[2] * W22;

        float K1s[4][3], Ka[4][3];
#pragma unroll
        for (int l = 0; l < 4; ++l) {
            K1s[l][0] = Pp[l][0] * G00 + Pp[l][1] * G10 + Pp[l][2] * G20;
            K1s[l][1] = Pp[l][0] * G01 + Pp[l][1] * G11 + Pp[l][2] * G21;
            K1s[l][2] = Pp[l][0] * G02 + Pp[l][1] * G12 + Pp[l][2] * G22;
            Ka[l][0] = K1s[l][0] * a1[0];
            Ka[l][1] = K1s[l][1] * a1[1];
            Ka[l][2] = K1s[l][2] * a1[2];
        }
        float eta1[4];
#pragma unroll
        for (int l = 0; l < 4; ++l)
            eta1[l] = ep[l] + K1s[l][0] * u0 + K1s[l][1] * u1 + K1s[l][2] * u2v;

        float P1u[10];
        {
            int idx = 0;
#pragma unroll
            for (int l = 0; l < 4; ++l)
#pragma unroll
                for (int j = 0; j < 4; ++j)
                    if (j >= l)
                        P1u[idx++] = Pp[l][j] - Ka[l][0] * Pp[0][j]
                                              - Ka[l][1] * Pp[1][j]
                                              - Ka[l][2] * Pp[2][j];
        }

        // ================= Regime 2: rank-1 Sherman-Morrison =================
        float s = Pp[3][3];
        float denom = 1.f + s * a2;
        float iden = __fdividef(1.f, denom);
        float k2[4], ak[4];
#pragma unroll
        for (int l = 0; l < 4; ++l) { k2[l] = Pp[l][3] * iden; ak[l] = a2 * k2[l]; }

        float lp2 = -0.5f * (quadD2 - s * u2s * u2s * iden + __logf(denom)) + CK;

        float eta2[4];
#pragma unroll
        for (int l = 0; l < 4; ++l) eta2[l] = ep[l] + k2[l] * u2s;

        float P2u[10];
        {
            int idx = 0;
#pragma unroll
            for (int l = 0; l < 4; ++l)
#pragma unroll
                for (int j = 0; j < 4; ++j)
                    if (j >= l)
                        P2u[idx++] = Pp[l][j] - ak[l] * Pp[3][j];
        }

        // ================= mixture collapse =================
        float lik1 = __expf(lp1);
        float lik2 = __expf(lp2);
        float num1 = lik1 * (p1 * p11);            // p21 = 0
        float num2 = lik2 * (p1 * p12 + p2);       // p22 = 1
        float marg = num1 + num2 + 1e-9f;
        float im = __fdividef(1.f, marg);
        float pt1 = num1 * im, pt2 = num2 * im;
        ll += (double)__logf(marg);

        float dd1[4], dd2[4];
#pragma unroll
        for (int l = 0; l < 4; ++l) {
            float e = pt1 * eta1[l] + pt2 * eta2[l];
            dd1[l] = eta1[l] - e;
            dd2[l] = eta2[l] - e;
            eta[l] = e;
        }
        {
            int idx = 0;
#pragma unroll
            for (int l = 0; l < 4; ++l)
#pragma unroll
                for (int j = 0; j < 4; ++j)
                    if (j >= l) {
                        float t1 = fmaf(dd1[l], dd1[j], P1u[idx]);
                        float t2 = fmaf(dd2[l], dd2[j], P2u[idx]);
                        float pn = pt1 * t1 + pt2 * t2;
                        P[l][j] = pn; P[j][l] = pn;
                        ++idx;
                    }
        }
        p1 = pt1; p2 = pt2;
#pragma unroll
        for (int o = 0; o < 9; ++o) yc[o] = yn[o];
    }

    // ---- deterministic reduction ----
    double v = ll;
#pragma unroll
    for (int off = 16; off > 0; off >>= 1)
        v += __shfl_down_sync(0xffffffffu, v, off);

    __shared__ double wsum[TPB / 32];
    if ((threadIdx.x & 31) == 0) wsum[threadIdx.x >> 5] = v;
    __syncthreads();
    if (threadIdx.x == 0) {
        double sacc = wsum[0];
#pragma unroll
        for (int w = 1; w < TPB / 32; ++w) sacc += wsum[w];
        g_partials[blockIdx.x] = sacc;
    }
}

__global__ void reduce_kernel(float* out)
{
    __shared__ double sh[NBLK];
    const int t = threadIdx.x;
    sh[t] = g_partials[t];
    __syncthreads();
    for (int k = NBLK / 2; k > 0; k >>= 1) {
        if (t < k) sh[t] += sh[t + k];
        __syncthreads();
    }
    if (t == 0) out[0] = (float)(-sh[0]);
}

extern "C" void kernel_launch(void* const* d_in, const int* in_sizes, int n_in,
                              void* d_out, int out_size)
{
    const float* y    = (const float*)d_in[0];
    const float* B1s1 = (const float*)d_in[1];
    const float* B1s2 = (const float*)d_in[2];
    const float* lam1 = (const float*)d_in[3];
    const float* lam2 = (const float*)d_in[4];
    const float* logq = (const float*)d_in[5];
    const float* logr = (const float*)d_in[6];
    const float* gami = (const float*)d_in[7];
    const float* gamc = (const float*)d_in[8];

    const int NT = in_sizes[0] / (NSER * OBS);   // 400

    kf_kernel<<<NBLK, TPB>>>(y, B1s1, B1s2, lam1, lam2, logq, logr, gami, gamc, NT);
    reduce_kernel<<<1, NBLK>>>((float*)d_out);
}

// round 7
// speedup vs baseline: 1.5912x; 1.2546x over previous
#include <cuda_runtime.h>

#define NSER 8192
#define OBS 9
#define NBLK 128
#define TPB 64
#define LOG2PI_F 1.8378770664093453f

static __device__ double g_partials[NBLK];

// 128 CTAs x 64 threads: <=1 CTA per SM, each CTA's 2 warps on distinct SMSPs
// -> 256 warps on 256 distinct SMSPs, no FMA-pipe sharing (R4 geometry).
__global__ void __launch_bounds__(TPB) kf_kernel(
    const float* __restrict__ y,
    const float* __restrict__ B1s1_p,
    const float* __restrict__ B1s2_p,
    const float* __restrict__ lam1_p,
    const float* __restrict__ lam2_p,
    const float* __restrict__ logq_p,
    const float* __restrict__ logr_p,
    const float* __restrict__ gami_p,
    const float* __restrict__ gamc_p,
    int NT)
{
    const int n = blockIdx.x * TPB + threadIdx.x;

    // ---------------- constants ----------------
    float B[3][3];
#pragma unroll
    for (int i = 0; i < 3; ++i)
#pragma unroll
        for (int j = 0; j < 3; ++j)
            B[i][j] = B1s1_p[i * 3 + j];
    const float b3 = B1s2_p[0];

    float q[4];
#pragma unroll
    for (int l = 0; l < 4; ++l) q[l] = expf(logq_p[l]);

    float c1[9], c2[9], dinv[9];
    c1[0] = 1.f; c1[1] = lam1_p[0]; c1[2] = lam1_p[1];
    c1[3] = 1.f; c1[4] = lam1_p[2]; c1[5] = lam1_p[3];
    c1[6] = 1.f; c1[7] = lam1_p[4]; c1[8] = lam1_p[5];
    c2[0] = 1.f;
#pragma unroll
    for (int o = 1; o < 9; ++o) c2[o] = lam2_p[o - 1];

    float logdetD = 0.f;
    float a1[3] = {0.f, 0.f, 0.f};
    float a2 = 0.f;
#pragma unroll
    for (int o = 0; o < 9; ++o) {
        float r = expf(logr_p[o]);
        float d = r + 1e-6f;
        float di = 1.f / d;
        dinv[o] = di;
        logdetD += logf(d);
        a1[o / 3] += c1[o] * c1[o] * di;   // U^T D^-1 U (diag, disjoint support)
        a2 += c2[o] * c2[o] * di;
    }
    const float CK = -0.5f * (9.f * LOG2PI_F + logdetD);   // constant part of logprob
    const float g0 = gami_p[0];
    const float gc0 = gamc_p[0], gc1 = gamc_p[1], gc2 = gamc_p[2];

    // ---------------- state ----------------
    float P[4][4];
#pragma unroll
    for (int i = 0; i < 4; ++i)
#pragma unroll
        for (int j = 0; j < 4; ++j)
            P[i][j] = (i == j) ? 1000.f : 0.f;
    float eta[4] = {0.f, 0.f, 0.f, 0.f};
    float p1 = 0.99f, p2 = 0.01f;
    double ll = 0.0;

    const float* yp = y + (size_t)n * NT * OBS;
    float yc[9];
#pragma unroll
    for (int o = 0; o < 9; ++o) yc[o] = yp[o];

#pragma unroll 1
    for (int t = 0; t < NT; ++t) {
        // ---- prefetch next step's observations (MLP=9, hides DRAM latency) ----
        float yn[9];
        {
            const float* ynp = yp + (t + 1) * OBS;
            const bool have = (t + 1) < NT;
#pragma unroll
            for (int o = 0; o < 9; ++o) yn[o] = have ? ynp[o] : 0.f;
        }

        // ---- transition prob (pre-update eta) ----
        float lg = g0 + gc0 * eta[0] + gc1 * eta[1] + gc2 * eta[2];
        float p11 = __fdividef(1.f, 1.f + __expf(-lg));
        float p12 = 1.f - p11;

        // ---- predict ----
        float ep[4];
        ep[0] = B[0][0] * eta[0] + B[0][1] * eta[1] + B[0][2] * eta[2];
        ep[1] = B[1][0] * eta[0] + B[1][1] * eta[1] + B[1][2] * eta[2];
        ep[2] = B[2][0] * eta[0] + B[2][1] * eta[1] + B[2][2] * eta[2];
        ep[3] = b3 * eta[3];

        float T[4][4];
#pragma unroll
        for (int i = 0; i < 3; ++i)
#pragma unroll
            for (int j = 0; j < 4; ++j)
                T[i][j] = B[i][0] * P[0][j] + B[i][1] * P[1][j] + B[i][2] * P[2][j];
#pragma unroll
        for (int j = 0; j < 4; ++j) T[3][j] = b3 * P[3][j];

        float Pp[4][4];
#pragma unroll
        for (int i = 0; i < 4; ++i) {
#pragma unroll
            for (int j = i; j < 4; ++j) {
                float v = (j < 3)
                        ? T[i][0] * B[j][0] + T[i][1] * B[j][1] + T[i][2] * B[j][2]
                        : T[i][3] * b3;
                Pp[i][j] = v; Pp[j][i] = v;
            }
        }
        Pp[0][0] += q[0]; Pp[1][1] += q[1]; Pp[2][2] += q[2]; Pp[3][3] += q[3];

        // ================= Regime 1: single-inverse Woodbury =================
        // S = I + M*diag(a1);  W = S^-1 M (symmetric);  detF1 = detD * detS
        float m00 = Pp[0][0], m01 = Pp[0][1], m02 = Pp[0][2];
        float m11 = Pp[1][1], m12 = Pp[1][2], m22 = Pp[2][2];
        float S00 = 1.f + m00 * a1[0], S01 = m01 * a1[1], S02 = m02 * a1[2];
        float S10 = m01 * a1[0], S11 = 1.f + m11 * a1[1], S12 = m12 * a1[2];
        float S20 = m02 * a1[0], S21 = m12 * a1[1], S22 = 1.f + m22 * a1[2];

        float adj00 = S11 * S22 - S12 * S21;
        float adj01 = S02 * S21 - S01 * S22;
        float adj02 = S01 * S12 - S02 * S11;
        float adj10 = S12 * S20 - S10 * S22;
        float adj11 = S00 * S22 - S02 * S20;
        float adj12 = S02 * S10 - S00 * S12;
        float adj20 = S10 * S21 - S11 * S20;
        float adj21 = S01 * S20 - S00 * S21;
        float adj22 = S00 * S11 - S01 * S10;
        float detS = S00 * adj00 + S01 * adj10 + S02 * adj20;
        float idS = __fdividef(1.f, detS);
        // rsqrt issues here, fully overlapped by the gain/P1u work below;
        // lik1 = exp(-0.5*quad1 + CK) / sqrt(detS)  (identical to exp(lp1))
        float rdetS;
        asm("rsqrt.approx.ftz.f32 %0, %1;" : "=f"(rdetS) : "f"(detS));

        float W00 = idS * (adj00 * m00 + adj01 * m01 + adj02 * m02);
        float W01 = idS * (adj00 * m01 + adj01 * m11 + adj02 * m12);
        float W02 = idS * (adj00 * m02 + adj01 * m12 + adj02 * m22);
        float W11 = idS * (adj10 * m01 + adj11 * m11 + adj12 * m12);
        float W12 = idS * (adj10 * m02 + adj11 * m12 + adj12 * m22);
        float W22 = idS * (adj20 * m02 + adj21 * m12 + adj22 * m22);

        // innovation, u = U^T D^-1 v, quadD = v^T D^-1 v
        float u0 = 0.f, u1 = 0.f, u2v = 0.f, quadD = 0.f;
#pragma unroll
        for (int o = 0; o < 9; ++o) {
            float v = yc[o] - c1[o] * ep[o / 3];
            float sv = v * dinv[o];
            quadD += v * sv;
            float csv = c1[o] * sv;
            if (o < 3) u0 += csv; else if (o < 6) u1 += csv; else u2v += csv;
        }
        float quad1 = quadD - (u0 * (W00 * u0 + W01 * u1 + W02 * u2v)
                             + u1 * (W01 * u0 + W11 * u1 + W12 * u2v)
                             + u2v * (W02 * u0 + W12 * u1 + W22 * u2v));

        // G = I - diag(a1) W (row-scaled); K1s = Pp[:,0:3] G
        float G00 = 1.f - a1[0] * W00, G01 = -a1[0] * W01, G02 = -a1[0] * W02;
        float G10 = -a1[1] * W01, G11 = 1.f - a1[1] * W11, G12 = -a1[1] * W12;
        float G20 = -a1[2] * W02, G21 = -a1[2] * W12, G22 = 1.f - a1[2] * W22;

        float K1s[4][3], Ka[4][3];
#pragma unroll
        for (int l = 0; l < 4; ++l) {
            K1s[l][0] = Pp[l][0] * G00 + Pp[l][1] * G10 + Pp[l][2] * G20;
            K1s[l][1] = Pp[l][0] * G01 + Pp[l][1] * G11 + Pp[l][2] * G21;
            K1s[l][2] = Pp[l][0] * G02 + Pp[l][1] * G12 + Pp[l][2] * G22;
            Ka[l][0] = K1s[l][0] * a1[0];
            Ka[l][1] = K1s[l][1] * a1[1];
            Ka[l][2] = K1s[l][2] * a1[2];
        }
        float eta1[4];
#pragma unroll
        for (int l = 0; l < 4; ++l)
            eta1[l] = ep[l] + K1s[l][0] * u0 + K1s[l][1] * u1 + K1s[l][2] * u2v;

        // short-form P1 = (I - K1 L1) Pp (Joseph delta = 1e-6*K K^T, negligible)
        float P1u[10];
        {
            int idx = 0;
#pragma unroll
            for (int l = 0; l < 4; ++l)
#pragma unroll
                for (int j = 0; j < 4; ++j)
                    if (j >= l)
                        P1u[idx++] = Pp[l][j] - Ka[l][0] * Pp[0][j]
                                              - Ka[l][1] * Pp[1][j]
                                              - Ka[l][2] * Pp[2][j];
        }

        // ================= Regime 2: rank-1 Sherman-Morrison =================
        float s = Pp[3][3];
        float denom = 1.f + s * a2;
        float iden = __fdividef(1.f, denom);
        float rden;
        asm("rsqrt.approx.ftz.f32 %0, %1;" : "=f"(rden) : "f"(denom));
        float k2[4], ak[4];
#pragma unroll
        for (int l = 0; l < 4; ++l) { k2[l] = Pp[l][3] * iden; ak[l] = a2 * k2[l]; }

        float u2s = 0.f, quadD2 = 0.f;
#pragma unroll
        for (int o = 0; o < 9; ++o) {
            float v = yc[o] - c2[o] * ep[3];
            float sv = v * dinv[o];
            quadD2 += v * sv;
            u2s += c2[o] * sv;
        }
        float quad2 = quadD2 - s * u2s * u2s * iden;

        float eta2[4];
#pragma unroll
        for (int l = 0; l < 4; ++l) eta2[l] = ep[l] + k2[l] * u2s;

        float P2u[10];
        {
            int idx = 0;
#pragma unroll
            for (int l = 0; l < 4; ++l)
#pragma unroll
                for (int j = 0; j < 4; ++j)
                    if (j >= l)
                        P2u[idx++] = Pp[l][j] - ak[l] * Pp[3][j];
        }

        // ================= mixture collapse =================
        // lik = exp(-0.5*quad + CK) * rsqrt(det) ; identical to exp(logprob)
        float lik1 = __expf(fmaf(-0.5f, quad1, CK)) * rdetS;
        float lik2 = __expf(fmaf(-0.5f, quad2, CK)) * rden;
        float num1 = lik1 * (p1 * p11);            // p21 = 0
        float num2 = lik2 * (p1 * p12 + p2);       // p22 = 1
        float marg = num1 + num2 + 1e-9f;
        float im = __fdividef(1.f, marg);
        float pt1 = num1 * im, pt2 = num2 * im;
        ll += (double)__logf(marg);

        float dd1[4], dd2[4];
#pragma unroll
        for (int l = 0; l < 4; ++l) {
            float e = pt1 * eta1[l] + pt2 * eta2[l];
            dd1[l] = eta1[l] - e;
            dd2[l] = eta2[l] - e;
            eta[l] = e;
        }
        {
            int idx = 0;
#pragma unroll
            for (int l = 0; l < 4; ++l)
#pragma unroll
                for (int j = 0; j < 4; ++j)
                    if (j >= l) {
                        float pn = pt1 * (P1u[idx] + dd1[l] * dd1[j])
                                 + pt2 * (P2u[idx] + dd2[l] * dd2[j]);
                        P[l][j] = pn; P[j][l] = pn;
                        ++idx;
                    }
        }
        p1 = pt1; p2 = pt2;
#pragma unroll
        for (int o = 0; o < 9; ++o) yc[o] = yn[o];
    }

    // ---- deterministic reduction: warp shuffle, then cross-warp via smem ----
    double v = ll;
#pragma unroll
    for (int off = 16; off > 0; off >>= 1)
        v += __shfl_down_sync(0xffffffffu, v, off);

    __shared__ double wsum[TPB / 32];
    if ((threadIdx.x & 31) == 0) wsum[threadIdx.x >> 5] = v;
    __syncthreads();
    if (threadIdx.x == 0) {
        double sacc = wsum[0];
#pragma unroll
        for (int w = 1; w < TPB / 32; ++w) sacc += wsum[w];
        g_partials[blockIdx.x] = sacc;
    }
}

__global__ void reduce_kernel(float* out)
{
    __shared__ double sh[NBLK];
    const int t = threadIdx.x;
    sh[t] = g_partials[t];
    __syncthreads();
    for (int k = NBLK / 2; k > 0; k >>= 1) {
        if (t < k) sh[t] += sh[t + k];
        __syncthreads();
    }
    if (t == 0) out[0] = (float)(-sh[0]);
}

extern "C" void kernel_launch(void* const* d_in, const int* in_sizes, int n_in,
                              void* d_out, int out_size)
{
    const float* y    = (const float*)d_in[0];
    const float* B1s1 = (const float*)d_in[1];
    const float* B1s2 = (const float*)d_in[2];
    const float* lam1 = (const float*)d_in[3];
    const float* lam2 = (const float*)d_in[4];
    const float* logq = (const float*)d_in[5];
    const float* logr = (const float*)d_in[6];
    const float* gami = (const float*)d_in[7];
    const float* gamc = (const float*)d_in[8];

    const int NT = in_sizes[0] / (NSER * OBS);   // 400

    kf_kernel<<<NBLK, TPB>>>(y, B1s1, B1s2, lam1, lam2, logq, logr, gami, gamc, NT);
    reduce_kernel<<<1, NBLK>>>((float*)d_out);
}